// round 8
// baseline (speedup 1.0000x reference)
#include <cuda_runtime.h>
#include <cuda_bf16.h>
#include <cstdint>

#define N_MAX 8192
#define D_MAX 256
#define BM 256                    // CTA rows (i)
#define BN 128                    // CTA cols (j)
#define BK 32                     // bf16 K per stage
#define NTHREADS 512
#define MARGIN 0.5f

__device__ __nv_bfloat16 g_xbf[N_MAX * D_MAX];
__device__ float g_sq[N_MAX];
__device__ int   g_is64;

// dynamic smem layout (bytes)
#define TILE_A_BYTES (BM * BK * 2)                  // 16384
#define TILE_B_BYTES (BN * BK * 2)                  // 8192
#define STAGE_BYTES  (TILE_A_BYTES + TILE_B_BYTES)  // 24576
#define SM_TILES 0
#define SM_SQI   (2 * STAGE_BYTES)                  // 49152
#define SM_SQJ   (SM_SQI + BM * 4)
#define SM_TI    (SM_SQJ + BN * 4)
#define SM_TJ    (SM_TI + BM * 4)
#define SM_RED   (SM_TJ + BN * 4)
#define SM_TOTAL (SM_RED + NTHREADS * 4)            // ~54.3 KB

__device__ __forceinline__ uint32_t smem_u32(const void* p) {
    uint32_t a;
    asm("{ .reg .u64 t; cvta.to.shared.u64 t, %1; cvt.u32.u64 %0, t; }" : "=r"(a) : "l"(p));
    return a;
}

// ---------------------------------------------------------------------------
// fused prelim: zero out + int64 detect + exact fp32 norms + bf16 copy
// ---------------------------------------------------------------------------
__global__ void cvtsq_kernel(const float* __restrict__ x,
                             const unsigned int* __restrict__ t, int n,
                             float* __restrict__ out) {
    if (blockIdx.x == 0 && threadIdx.x < 32) {
        int lane = threadIdx.x;
        unsigned bad = t[2 * lane + 1] | t[2 * (lane + 32) + 1];
        unsigned ball = __ballot_sync(0xffffffffu, bad != 0u);
        if (lane == 0) { g_is64 = (ball == 0u); out[0] = 0.0f; }
    }

    int row  = blockIdx.x * (blockDim.x >> 5) + (threadIdx.x >> 5);
    int lane = threadIdx.x & 31;
    if (row >= n) return;
    const float* p = x + (size_t)row * D_MAX;

    float4 v0 = *(const float4*)(p + lane * 4);
    float4 v1 = *(const float4*)(p + 128 + lane * 4);

    float s = v0.x * v0.x + v0.y * v0.y + v0.z * v0.z + v0.w * v0.w
            + v1.x * v1.x + v1.y * v1.y + v1.z * v1.z + v1.w * v1.w;
    #pragma unroll
    for (int o = 16; o > 0; o >>= 1) s += __shfl_xor_sync(0xffffffffu, s, o);
    if (lane == 0) g_sq[row] = s;

    __nv_bfloat16* dst = g_xbf + (size_t)row * D_MAX;
    *(__nv_bfloat162*)(dst + lane * 4)           = __floats2bfloat162_rn(v0.x, v0.y);
    *(__nv_bfloat162*)(dst + lane * 4 + 2)       = __floats2bfloat162_rn(v0.z, v0.w);
    *(__nv_bfloat162*)(dst + 128 + lane * 4)     = __floats2bfloat162_rn(v1.x, v1.y);
    *(__nv_bfloat162*)(dst + 128 + lane * 4 + 2) = __floats2bfloat162_rn(v1.z, v1.w);
}

// ---------------------------------------------------------------------------
// bf16 mma.sync fused gram + loss. CTA tile 256x128, 16 warps (4m x 4n),
// warp tile 64x32. CTA(bi,bj): rows [256bi,256bi+256), cols [128bj,128bj+128),
// bj in [2bi, 64). Every unordered pair (gi<gj) covered exactly once.
// smem rows: 64B stride; 16B chunk c of row r at r*64 + ((c^(r&3))<<4).
// ---------------------------------------------------------------------------
__global__ __launch_bounds__(NTHREADS, 1)
void loss_kernel(const void* __restrict__ tgt_raw, float* __restrict__ out,
                 int ntM, int ntN, float scale) {
    // decode t -> (bi, bj): start(bi) = 64*bi - bi*(bi-1)
    const int t = blockIdx.x;
    int bi = 0;
    {
        // float guess then fix (ntM<=32 so loop is tiny anyway)
        float ft = (float)t;
        bi = (int)((65.0f - sqrtf(65.0f * 65.0f - 4.0f * (64.0f + ft))) * 0.5f);
        if (bi < 0) bi = 0;
        if (bi > ntM - 1) bi = ntM - 1;
        while (bi + 1 <= ntM - 1 && (ntN * (bi + 1) - (bi + 1) * bi) <= t) bi++;
        while (ntN * bi - bi * (bi - 1) > t) bi--;
    }
    const int bj = 2 * bi + (t - (ntN * bi - bi * (bi - 1)));

    extern __shared__ char smem[];
    float* s_sqi = (float*)(smem + SM_SQI);
    float* s_sqj = (float*)(smem + SM_SQJ);
    int*   s_ti  = (int*)(smem + SM_TI);
    int*   s_tj  = (int*)(smem + SM_TJ);
    float* s_red = (float*)(smem + SM_RED);

    const int tid  = threadIdx.x;
    const int wid  = tid >> 5;
    const int lane = tid & 31;
    const int iBase = bi * BM;
    const int jBase = bj * BN;

    {
        const long long* t64p = (const long long*)tgt_raw;
        const int*       t32p = (const int*)tgt_raw;
        const bool is64 = (g_is64 != 0);
        if (tid < BM) {
            s_sqi[tid] = g_sq[iBase + tid];
            s_ti[tid]  = is64 ? (int)t64p[iBase + tid] : t32p[iBase + tid];
        } else if (tid < BM + BN) {
            int tt = tid - BM;
            s_sqj[tt] = g_sq[jBase + tt];
            s_tj[tt]  = is64 ? (int)t64p[jBase + tt] : t32p[jBase + tt];
        }
    }

    const uint32_t smem_tiles = smem_u32(smem);
    const __nv_bfloat16* xa = g_xbf + (size_t)iBase * D_MAX;
    const __nv_bfloat16* xb = g_xbf + (size_t)jBase * D_MAX;

    // per stage: A = 1024 16B-chunks (2/thread), B = 512 chunks (1/thread)
    auto load_stage = [&](int kb, int stage) {
        const int k0 = kb * BK;
        const uint32_t sA = smem_tiles + stage * STAGE_BYTES;
        const uint32_t sB = sA + TILE_A_BYTES;
        #pragma unroll
        for (int u = 0; u < 2; u++) {
            int idx = tid * 2 + u;           // 0..1023
            int row = idx >> 2;              // 0..255
            int c   = idx & 3;
            uint32_t sw = row * 64 + (((c ^ (row & 3)) & 3) << 4);
            asm volatile("cp.async.cg.shared.global [%0], [%1], 16;"
                         :: "r"(sA + sw), "l"((const void*)(xa + row * D_MAX + k0 + c * 8)) : "memory");
        }
        {
            int row = tid >> 2;              // 0..127
            int c   = tid & 3;
            uint32_t sw = row * 64 + (((c ^ (row & 3)) & 3) << 4);
            asm volatile("cp.async.cg.shared.global [%0], [%1], 16;"
                         :: "r"(sB + sw), "l"((const void*)(xb + row * D_MAX + k0 + c * 8)) : "memory");
        }
        asm volatile("cp.async.commit_group;" ::: "memory");
    };

    // warp grid 4m x 4n; warp tile 64 x 32
    const int mbase = (wid >> 2) * 64;
    const int nbase = (wid & 3) * 32;

    float acc[4][4][4];
    #pragma unroll
    for (int mt = 0; mt < 4; mt++)
        #pragma unroll
        for (int ntl = 0; ntl < 4; ntl++)
            #pragma unroll
            for (int r = 0; r < 4; r++) acc[mt][ntl][r] = 0.0f;

    // ldmatrix lane -> (row, 16B-chunk) components (validated R3/R4/R7)
    const int a_roff = ((lane >> 3) & 1) * 8 + (lane & 7);
    const int a_coff = (lane >> 4);
    const int b_roff = ((lane >> 4) & 1) * 8 + (lane & 7);
    const int b_coff = ((lane >> 3) & 1);

    load_stage(0, 0);

    const int NKB = D_MAX / BK;   // 8
    for (int kb = 0; kb < NKB; kb++) {
        if (kb + 1 < NKB) {
            load_stage(kb + 1, (kb + 1) & 1);
            asm volatile("cp.async.wait_group 1;" ::: "memory");
        } else {
            asm volatile("cp.async.wait_group 0;" ::: "memory");
        }
        __syncthreads();

        const uint32_t sA = smem_tiles + (kb & 1) * STAGE_BYTES;
        const uint32_t sB = sA + TILE_A_BYTES;

        #pragma unroll
        for (int ks = 0; ks < 2; ks++) {          // two k16 steps per stage
            uint32_t a[4][4];
            #pragma unroll
            for (int mt = 0; mt < 4; mt++) {
                int r = mbase + mt * 16 + a_roff;
                int c = a_coff + 2 * ks;
                uint32_t addr = sA + r * 64 + (((c ^ (r & 3)) & 3) << 4);
                asm volatile("ldmatrix.sync.aligned.m8n8.x4.shared.b16 {%0,%1,%2,%3}, [%4];"
                             : "=r"(a[mt][0]), "=r"(a[mt][1]), "=r"(a[mt][2]), "=r"(a[mt][3])
                             : "r"(addr));
            }
            uint32_t bfr[4][2];
            #pragma unroll
            for (int p = 0; p < 2; p++) {
                int r = nbase + p * 16 + b_roff;
                int c = b_coff + 2 * ks;
                uint32_t addr = sB + r * 64 + (((c ^ (r & 3)) & 3) << 4);
                asm volatile("ldmatrix.sync.aligned.m8n8.x4.shared.b16 {%0,%1,%2,%3}, [%4];"
                             : "=r"(bfr[2 * p][0]), "=r"(bfr[2 * p][1]),
                               "=r"(bfr[2 * p + 1][0]), "=r"(bfr[2 * p + 1][1])
                             : "r"(addr));
            }
            #pragma unroll
            for (int mt = 0; mt < 4; mt++)
                #pragma unroll
                for (int ntl = 0; ntl < 4; ntl++)
                    asm volatile(
                        "mma.sync.aligned.m16n8k16.row.col.f32.bf16.bf16.f32 "
                        "{%0,%1,%2,%3}, {%4,%5,%6,%7}, {%8,%9}, {%0,%1,%2,%3};"
                        : "+f"(acc[mt][ntl][0]), "+f"(acc[mt][ntl][1]),
                          "+f"(acc[mt][ntl][2]), "+f"(acc[mt][ntl][3])
                        : "r"(a[mt][0]), "r"(a[mt][1]), "r"(a[mt][2]), "r"(a[mt][3]),
                          "r"(bfr[ntl][0]), "r"(bfr[ntl][1]));
        }
        __syncthreads();
    }

    // epilogue: dist -> hinge/mask -> sum over pairs with gi < gj
    const int gid = lane >> 2;
    const int tig = lane & 3;
    const bool need_mask = (bj < 2 * bi + 2);   // only edge CTAs touch gi>=gj
    float lsum = 0.0f;
    #pragma unroll
    for (int mt = 0; mt < 4; mt++) {
        #pragma unroll
        for (int ntl = 0; ntl < 4; ntl++) {
            #pragma unroll
            for (int r = 0; r < 4; r++) {
                int m  = mbase + mt * 16 + gid + ((r >> 1) << 3);
                int nn = nbase + ntl * 8 + 2 * tig + (r & 1);
                float g    = acc[mt][ntl][r];
                float dist = fmaf(-2.0f, g, s_sqi[m] + s_sqj[nn]);
                float val  = (s_ti[m] == s_tj[nn]) ? dist : fmaxf(MARGIN - dist, 0.0f);
                if (!need_mask || (iBase + m < jBase + nn)) lsum += val;
            }
        }
    }

    s_red[tid] = lsum;
    __syncthreads();
    #pragma unroll
    for (int s = NTHREADS / 2; s > 32; s >>= 1) {
        if (tid < s) s_red[tid] += s_red[tid + s];
        __syncthreads();
    }
    if (tid < 32) {
        float v = s_red[tid] + s_red[tid + 32];
        #pragma unroll
        for (int o = 16; o > 0; o >>= 1) v += __shfl_xor_sync(0xffffffffu, v, o);
        if (tid == 0) atomicAdd(out, v * scale);
    }
}

extern "C" void kernel_launch(void* const* d_in, const int* in_sizes, int n_in,
                              void* d_out, int out_size) {
    const float* x   = (const float*)d_in[0];
    const void*  tgt = d_in[1];
    float*       out = (float*)d_out;

    int n = in_sizes[1];            // 8192
    int ntM = n / BM;               // 32
    int ntN = n / BN;               // 64
    // grid = sum_{bi<ntM} (ntN - 2*bi)
    int ngrid = ntM * ntN - ntM * (ntM - 1);   // 2048 - 992 = 1056

    static int smem_set = 0;
    if (!smem_set) {
        cudaFuncSetAttribute(loss_kernel, cudaFuncAttributeMaxDynamicSharedMemorySize, SM_TOTAL);
        smem_set = 1;
    }

    cvtsq_kernel<<<(n + 7) / 8, 256>>>(x, (const unsigned int*)tgt, n, out);

    float scale = (float)(1.0 / ((double)n * ((double)n - 1.0)));
    loss_kernel<<<ngrid, NTHREADS, SM_TOTAL>>>(tgt, out, ntM, ntN, scale);
}

// round 9
// speedup vs baseline: 1.1299x; 1.1299x over previous
#include <cuda_runtime.h>
#include <cuda_bf16.h>
#include <cstdint>

#define N_MAX 8192
#define D_MAX 256
#define BM 256                    // CTA rows (i)
#define BN 128                    // CTA cols (j)
#define BK 64                     // bf16 K per stage
#define NKB 4                     // K stages = 256/64
#define NBUF 3                    // smem buffers
#define NTHREADS 512
#define MARGIN 0.5f

__device__ __nv_bfloat16 g_xbf[N_MAX * D_MAX];
__device__ float g_sq[N_MAX];
__device__ int   g_is64;

// dynamic smem layout (bytes)
#define TILE_A_BYTES (BM * BK * 2)                  // 32768
#define TILE_B_BYTES (BN * BK * 2)                  // 16384
#define STAGE_BYTES  (TILE_A_BYTES + TILE_B_BYTES)  // 49152
#define SM_SQI   (NBUF * STAGE_BYTES)               // 147456
#define SM_SQJ   (SM_SQI + BM * 4)
#define SM_TI    (SM_SQJ + BN * 4)
#define SM_TJ    (SM_TI + BM * 4)
#define SM_RED   (SM_TJ + BN * 4)
#define SM_TOTAL (SM_RED + NTHREADS * 4)            // ~149.3 KB

__device__ __forceinline__ uint32_t smem_u32(const void* p) {
    uint32_t a;
    asm("{ .reg .u64 t; cvta.to.shared.u64 t, %1; cvt.u32.u64 %0, t; }" : "=r"(a) : "l"(p));
    return a;
}

// ---------------------------------------------------------------------------
// fused prelim: zero out + int64 detect + exact fp32 norms + bf16 copy
// ---------------------------------------------------------------------------
__global__ void cvtsq_kernel(const float* __restrict__ x,
                             const unsigned int* __restrict__ t, int n,
                             float* __restrict__ out) {
    if (blockIdx.x == 0 && threadIdx.x < 32) {
        int lane = threadIdx.x;
        unsigned bad = t[2 * lane + 1] | t[2 * (lane + 32) + 1];
        unsigned ball = __ballot_sync(0xffffffffu, bad != 0u);
        if (lane == 0) { g_is64 = (ball == 0u); out[0] = 0.0f; }
    }

    int row  = blockIdx.x * (blockDim.x >> 5) + (threadIdx.x >> 5);
    int lane = threadIdx.x & 31;
    if (row >= n) return;
    const float* p = x + (size_t)row * D_MAX;

    float4 v0 = *(const float4*)(p + lane * 4);
    float4 v1 = *(const float4*)(p + 128 + lane * 4);

    float s = v0.x * v0.x + v0.y * v0.y + v0.z * v0.z + v0.w * v0.w
            + v1.x * v1.x + v1.y * v1.y + v1.z * v1.z + v1.w * v1.w;
    #pragma unroll
    for (int o = 16; o > 0; o >>= 1) s += __shfl_xor_sync(0xffffffffu, s, o);
    if (lane == 0) g_sq[row] = s;

    __nv_bfloat16* dst = g_xbf + (size_t)row * D_MAX;
    *(__nv_bfloat162*)(dst + lane * 4)           = __floats2bfloat162_rn(v0.x, v0.y);
    *(__nv_bfloat162*)(dst + lane * 4 + 2)       = __floats2bfloat162_rn(v0.z, v0.w);
    *(__nv_bfloat162*)(dst + 128 + lane * 4)     = __floats2bfloat162_rn(v1.x, v1.y);
    *(__nv_bfloat162*)(dst + 128 + lane * 4 + 2) = __floats2bfloat162_rn(v1.z, v1.w);
}

// ---------------------------------------------------------------------------
// bf16 mma.sync fused gram + loss. CTA 256x128, 16 warps 4m x 4n, warp 64x32.
// 3-deep cp.async stage buffering + register fragment double-buffering.
// smem rows: 128B stride (BK=64); 16B chunk c of row r at r*128 + ((c^(r&7))<<4).
// ---------------------------------------------------------------------------
__global__ __launch_bounds__(NTHREADS, 1)
void loss_kernel(const void* __restrict__ tgt_raw, float* __restrict__ out,
                 int ntM, int ntN, float scale) {
    // decode t -> (bi, bj): start(bi) = 64*bi - bi*(bi-1), bj in [2bi, 64)
    const int t = blockIdx.x;
    int bi = 0;
    {
        float ft = (float)t;
        bi = (int)((65.0f - sqrtf(65.0f * 65.0f - 4.0f * (64.0f + ft))) * 0.5f);
        if (bi < 0) bi = 0;
        if (bi > ntM - 1) bi = ntM - 1;
        while (bi + 1 <= ntM - 1 && (ntN * (bi + 1) - (bi + 1) * bi) <= t) bi++;
        while (ntN * bi - bi * (bi - 1) > t) bi--;
    }
    const int bj = 2 * bi + (t - (ntN * bi - bi * (bi - 1)));

    extern __shared__ char smem[];
    float* s_sqi = (float*)(smem + SM_SQI);
    float* s_sqj = (float*)(smem + SM_SQJ);
    int*   s_ti  = (int*)(smem + SM_TI);
    int*   s_tj  = (int*)(smem + SM_TJ);
    float* s_red = (float*)(smem + SM_RED);

    const int tid  = threadIdx.x;
    const int wid  = tid >> 5;
    const int lane = tid & 31;
    const int iBase = bi * BM;
    const int jBase = bj * BN;

    const uint32_t smem_tiles = smem_u32(smem);
    const __nv_bfloat16* xa = g_xbf + (size_t)iBase * D_MAX;
    const __nv_bfloat16* xb = g_xbf + (size_t)jBase * D_MAX;

    // A: 2048 16B-chunks (4/thread), B: 1024 (2/thread); row=idx>>3, c=idx&7
    auto load_stage = [&](int kb, int buf) {
        const int k0 = kb * BK;
        const uint32_t sA = smem_tiles + buf * STAGE_BYTES;
        const uint32_t sB = sA + TILE_A_BYTES;
        #pragma unroll
        for (int u = 0; u < 4; u++) {
            int idx = tid * 4 + u;
            int row = idx >> 3;
            int c   = idx & 7;
            uint32_t sw = row * 128 + (((c ^ (row & 7)) & 7) << 4);
            asm volatile("cp.async.cg.shared.global [%0], [%1], 16;"
                         :: "r"(sA + sw), "l"((const void*)(xa + row * D_MAX + k0 + c * 8)) : "memory");
        }
        #pragma unroll
        for (int u = 0; u < 2; u++) {
            int idx = tid * 2 + u;
            int row = idx >> 3;
            int c   = idx & 7;
            uint32_t sw = row * 128 + (((c ^ (row & 7)) & 7) << 4);
            asm volatile("cp.async.cg.shared.global [%0], [%1], 16;"
                         :: "r"(sB + sw), "l"((const void*)(xb + row * D_MAX + k0 + c * 8)) : "memory");
        }
        asm volatile("cp.async.commit_group;" ::: "memory");
    };

    // prologue loads first so metadata LDGs overlap them
    load_stage(0, 0);
    load_stage(1, 1);
    load_stage(2, 2);

    {
        const long long* t64p = (const long long*)tgt_raw;
        const int*       t32p = (const int*)tgt_raw;
        const bool is64 = (g_is64 != 0);
        if (tid < BM) {
            s_sqi[tid] = g_sq[iBase + tid];
            s_ti[tid]  = is64 ? (int)t64p[iBase + tid] : t32p[iBase + tid];
        } else if (tid < BM + BN) {
            int tt = tid - BM;
            s_sqj[tt] = g_sq[jBase + tt];
            s_tj[tt]  = is64 ? (int)t64p[jBase + tt] : t32p[jBase + tt];
        }
    }

    // warp grid 4m x 4n; warp tile 64 x 32
    const int mbase = (wid >> 2) * 64;
    const int nbase = (wid & 3) * 32;

    float acc[4][4][4];
    #pragma unroll
    for (int mt = 0; mt < 4; mt++)
        #pragma unroll
        for (int ntl = 0; ntl < 4; ntl++)
            #pragma unroll
            for (int r = 0; r < 4; r++) acc[mt][ntl][r] = 0.0f;

    // ldmatrix lane -> (row, chunk) mapping (validated R3/R7/R8)
    const int a_roff = ((lane >> 3) & 1) * 8 + (lane & 7);
    const int a_coff = (lane >> 4);
    const int b_roff = ((lane >> 4) & 1) * 8 + (lane & 7);
    const int b_coff = ((lane >> 3) & 1);

    uint32_t aF[2][4][4];   // fragment double buffer
    uint32_t bF[2][4][2];

    auto ldm_frags = [&](int d, int buf, int s) {
        const uint32_t sA = smem_tiles + buf * STAGE_BYTES;
        const uint32_t sB = sA + TILE_A_BYTES;
        #pragma unroll
        for (int mt = 0; mt < 4; mt++) {
            int r  = mbase + mt * 16 + a_roff;
            int ch = a_coff + 2 * s;
            uint32_t addr = sA + r * 128 + (((ch ^ (r & 7)) & 7) << 4);
            asm volatile("ldmatrix.sync.aligned.m8n8.x4.shared.b16 {%0,%1,%2,%3}, [%4];"
                         : "=r"(aF[d][mt][0]), "=r"(aF[d][mt][1]),
                           "=r"(aF[d][mt][2]), "=r"(aF[d][mt][3])
                         : "r"(addr));
        }
        #pragma unroll
        for (int p = 0; p < 2; p++) {
            int r  = nbase + p * 16 + b_roff;
            int ch = b_coff + 2 * s;
            uint32_t addr = sB + r * 128 + (((ch ^ (r & 7)) & 7) << 4);
            asm volatile("ldmatrix.sync.aligned.m8n8.x4.shared.b16 {%0,%1,%2,%3}, [%4];"
                         : "=r"(bF[d][2 * p][0]), "=r"(bF[d][2 * p][1]),
                           "=r"(bF[d][2 * p + 1][0]), "=r"(bF[d][2 * p + 1][1])
                         : "r"(addr));
        }
    };

    auto mma_all = [&](int d) {
        #pragma unroll
        for (int mt = 0; mt < 4; mt++)
            #pragma unroll
            for (int ntl = 0; ntl < 4; ntl++)
                asm volatile(
                    "mma.sync.aligned.m16n8k16.row.col.f32.bf16.bf16.f32 "
                    "{%0,%1,%2,%3}, {%4,%5,%6,%7}, {%8,%9}, {%0,%1,%2,%3};"
                    : "+f"(acc[mt][ntl][0]), "+f"(acc[mt][ntl][1]),
                      "+f"(acc[mt][ntl][2]), "+f"(acc[mt][ntl][3])
                    : "r"(aF[d][mt][0]), "r"(aF[d][mt][1]),
                      "r"(aF[d][mt][2]), "r"(aF[d][mt][3]),
                      "r"(bF[d][ntl][0]), "r"(bF[d][ntl][1]));
    };

    asm volatile("cp.async.wait_group 2;" ::: "memory");   // stage 0 ready
    __syncthreads();
    ldm_frags(0, 0, 0);

    // 16 k16 steps; stage = kk>>2 (buffer stage%3), step-in-stage = kk&3
    #pragma unroll
    for (int kk = 0; kk < 16; kk++) {
        const int cur = kk & 1, nxt = cur ^ 1;
        const int stage = kk >> 2, spos = kk & 3;
        if (kk < 15) {
            if (spos == 3) {
                // boundary: stage+1's buffer must be resident
                if (stage < 2) { asm volatile("cp.async.wait_group 1;" ::: "memory"); }
                else           { asm volatile("cp.async.wait_group 0;" ::: "memory"); }
                __syncthreads();                 // all warps done with buffer stage%3
                if (stage == 0) load_stage(3, 0);  // reuse buffer 0
                ldm_frags(nxt, (stage + 1) % 3, 0);
            } else {
                ldm_frags(nxt, stage % 3, spos + 1);
            }
        }
        mma_all(cur);
    }

    // epilogue: dist -> hinge/mask -> sum over pairs gi < gj
    const int gid = lane >> 2;
    const int tig = lane & 3;
    const bool need_mask = (bj < 2 * bi + 2);
    float lsum = 0.0f;
    #pragma unroll
    for (int mt = 0; mt < 4; mt++) {
        #pragma unroll
        for (int ntl = 0; ntl < 4; ntl++) {
            #pragma unroll
            for (int r = 0; r < 4; r++) {
                int m  = mbase + mt * 16 + gid + ((r >> 1) << 3);
                int nn = nbase + ntl * 8 + 2 * tig + (r & 1);
                float g    = acc[mt][ntl][r];
                float dist = fmaf(-2.0f, g, s_sqi[m] + s_sqj[nn]);
                float val  = (s_ti[m] == s_tj[nn]) ? dist : fmaxf(MARGIN - dist, 0.0f);
                if (!need_mask || (iBase + m < jBase + nn)) lsum += val;
            }
        }
    }

    s_red[tid] = lsum;
    __syncthreads();
    #pragma unroll
    for (int s = NTHREADS / 2; s > 32; s >>= 1) {
        if (tid < s) s_red[tid] += s_red[tid + s];
        __syncthreads();
    }
    if (tid < 32) {
        float v = s_red[tid] + s_red[tid + 32];
        #pragma unroll
        for (int o = 16; o > 0; o >>= 1) v += __shfl_xor_sync(0xffffffffu, v, o);
        if (tid == 0) atomicAdd(out, v * scale);
    }
}

extern "C" void kernel_launch(void* const* d_in, const int* in_sizes, int n_in,
                              void* d_out, int out_size) {
    const float* x   = (const float*)d_in[0];
    const void*  tgt = d_in[1];
    float*       out = (float*)d_out;

    int n = in_sizes[1];            // 8192
    int ntM = n / BM;               // 32
    int ntN = n / BN;               // 64
    int ngrid = ntM * ntN - ntM * (ntM - 1);   // 1056

    static int smem_set = 0;
    if (!smem_set) {
        cudaFuncSetAttribute(loss_kernel, cudaFuncAttributeMaxDynamicSharedMemorySize, SM_TOTAL);
        smem_set = 1;
    }

    cvtsq_kernel<<<(n + 7) / 8, 256>>>(x, (const unsigned int*)tgt, n, out);

    float scale = (float)(1.0 / ((double)n * ((double)n - 1.0)));
    loss_kernel<<<ngrid, NTHREADS, SM_TOTAL>>>(tgt, out, ntM, ntN, scale);
}

// round 10
// speedup vs baseline: 1.1925x; 1.0554x over previous
#include <cuda_runtime.h>
#include <cuda_fp16.h>
#include <cstdint>

#define N_MAX 8192
#define D_MAX 256
#define BM 256                    // CTA rows (i)
#define BN 128                    // CTA cols (j)
#define BK 64                     // f16 K per stage
#define NBUF 3                    // smem stage buffers
#define NTHREADS 512
#define MARGIN 0.5f

__device__ __half g_xh[N_MAX * D_MAX];
__device__ float g_sq[N_MAX];
__device__ int   g_is64;

// dynamic smem layout (bytes)
#define TILE_A_BYTES (BM * BK * 2)                  // 32768
#define TILE_B_BYTES (BN * BK * 2)                  // 16384
#define STAGE_BYTES  (TILE_A_BYTES + TILE_B_BYTES)  // 49152
#define SM_SQI   (NBUF * STAGE_BYTES)               // 147456
#define SM_SQJ   (SM_SQI + BM * 4)
#define SM_TI    (SM_SQJ + BN * 4)
#define SM_TJ    (SM_TI + BM * 4)
#define SM_RED   (SM_TJ + BN * 4)
#define SM_TOTAL (SM_RED + NTHREADS * 4)            // ~149.3 KB

__device__ __forceinline__ uint32_t smem_u32(const void* p) {
    uint32_t a;
    asm("{ .reg .u64 t; cvta.to.shared.u64 t, %1; cvt.u32.u64 %0, t; }" : "=r"(a) : "l"(p));
    return a;
}

// ---------------------------------------------------------------------------
// fused prelim: zero out + int64 detect + exact fp32 norms + f16 copy
// ---------------------------------------------------------------------------
__global__ void cvtsq_kernel(const float* __restrict__ x,
                             const unsigned int* __restrict__ t, int n,
                             float* __restrict__ out) {
    if (blockIdx.x == 0 && threadIdx.x < 32) {
        int lane = threadIdx.x;
        unsigned bad = t[2 * lane + 1] | t[2 * (lane + 32) + 1];
        unsigned ball = __ballot_sync(0xffffffffu, bad != 0u);
        if (lane == 0) { g_is64 = (ball == 0u); out[0] = 0.0f; }
    }

    int row  = blockIdx.x * (blockDim.x >> 5) + (threadIdx.x >> 5);
    int lane = threadIdx.x & 31;
    if (row >= n) return;
    const float* p = x + (size_t)row * D_MAX;

    float4 v0 = *(const float4*)(p + lane * 4);
    float4 v1 = *(const float4*)(p + 128 + lane * 4);

    float s = v0.x * v0.x + v0.y * v0.y + v0.z * v0.z + v0.w * v0.w
            + v1.x * v1.x + v1.y * v1.y + v1.z * v1.z + v1.w * v1.w;
    #pragma unroll
    for (int o = 16; o > 0; o >>= 1) s += __shfl_xor_sync(0xffffffffu, s, o);
    if (lane == 0) g_sq[row] = s;

    __half* dst = g_xh + (size_t)row * D_MAX;
    *(__half2*)(dst + lane * 4)           = __floats2half2_rn(v0.x, v0.y);
    *(__half2*)(dst + lane * 4 + 2)       = __floats2half2_rn(v0.z, v0.w);
    *(__half2*)(dst + 128 + lane * 4)     = __floats2half2_rn(v1.x, v1.y);
    *(__half2*)(dst + 128 + lane * 4 + 2) = __floats2half2_rn(v1.z, v1.w);
}

// ---------------------------------------------------------------------------
// f16 mma.sync (f16 accum) fused gram + loss. CTA 256x128, 16 warps 4m x 4n,
// warp tile 64x32. 3-deep cp.async buffering + register fragment double-buffer.
// smem rows: 128B stride; 16B chunk c of row r at r*128 + ((c^(r&7))<<4).
// ---------------------------------------------------------------------------
__global__ __launch_bounds__(NTHREADS, 1)
void loss_kernel(const void* __restrict__ tgt_raw, float* __restrict__ out,
                 int ntM, int ntN, float scale) {
    // decode t -> (bi, bj): start(bi) = 64*bi - bi*(bi-1), bj in [2bi, 64)
    const int t = blockIdx.x;
    int bi = 0;
    {
        float ft = (float)t;
        bi = (int)((65.0f - sqrtf(65.0f * 65.0f - 4.0f * (64.0f + ft))) * 0.5f);
        if (bi < 0) bi = 0;
        if (bi > ntM - 1) bi = ntM - 1;
        while (bi + 1 <= ntM - 1 && (ntN * (bi + 1) - (bi + 1) * bi) <= t) bi++;
        while (ntN * bi - bi * (bi - 1) > t) bi--;
    }
    const int bj = 2 * bi + (t - (ntN * bi - bi * (bi - 1)));

    extern __shared__ char smem[];
    float* s_sqi = (float*)(smem + SM_SQI);
    float* s_sqj = (float*)(smem + SM_SQJ);
    int*   s_ti  = (int*)(smem + SM_TI);
    int*   s_tj  = (int*)(smem + SM_TJ);
    float* s_red = (float*)(smem + SM_RED);

    const int tid  = threadIdx.x;
    const int wid  = tid >> 5;
    const int lane = tid & 31;
    const int iBase = bi * BM;
    const int jBase = bj * BN;

    const uint32_t smem_tiles = smem_u32(smem);
    const __half* xa = g_xh + (size_t)iBase * D_MAX;
    const __half* xb = g_xh + (size_t)jBase * D_MAX;

    auto load_stage = [&](int kb, int buf) {
        const int k0 = kb * BK;
        const uint32_t sA = smem_tiles + buf * STAGE_BYTES;
        const uint32_t sB = sA + TILE_A_BYTES;
        #pragma unroll
        for (int u = 0; u < 4; u++) {
            int idx = tid * 4 + u;
            int row = idx >> 3;
            int c   = idx & 7;
            uint32_t sw = row * 128 + (((c ^ (row & 7)) & 7) << 4);
            asm volatile("cp.async.cg.shared.global [%0], [%1], 16;"
                         :: "r"(sA + sw), "l"((const void*)(xa + row * D_MAX + k0 + c * 8)) : "memory");
        }
        #pragma unroll
        for (int u = 0; u < 2; u++) {
            int idx = tid * 2 + u;
            int row = idx >> 3;
            int c   = idx & 7;
            uint32_t sw = row * 128 + (((c ^ (row & 7)) & 7) << 4);
            asm volatile("cp.async.cg.shared.global [%0], [%1], 16;"
                         :: "r"(sB + sw), "l"((const void*)(xb + row * D_MAX + k0 + c * 8)) : "memory");
        }
        asm volatile("cp.async.commit_group;" ::: "memory");
    };

    load_stage(0, 0);
    load_stage(1, 1);
    load_stage(2, 2);

    {
        const long long* t64p = (const long long*)tgt_raw;
        const int*       t32p = (const int*)tgt_raw;
        const bool is64 = (g_is64 != 0);
        if (tid < BM) {
            s_sqi[tid] = g_sq[iBase + tid];
            s_ti[tid]  = is64 ? (int)t64p[iBase + tid] : t32p[iBase + tid];
        } else if (tid < BM + BN) {
            int tt = tid - BM;
            s_sqj[tt] = g_sq[jBase + tt];
            s_tj[tt]  = is64 ? (int)t64p[jBase + tt] : t32p[jBase + tt];
        }
    }

    // warp grid 4m x 4n; warp tile 64 x 32
    const int mbase = (wid >> 2) * 64;
    const int nbase = (wid & 3) * 32;

    uint32_t acc[4][4][2];        // f16x2 pairs; 0 bits == (0h, 0h)
    #pragma unroll
    for (int mt = 0; mt < 4; mt++)
        #pragma unroll
        for (int ntl = 0; ntl < 4; ntl++) { acc[mt][ntl][0] = 0u; acc[mt][ntl][1] = 0u; }

    const int a_roff = ((lane >> 3) & 1) * 8 + (lane & 7);
    const int a_coff = (lane >> 4);
    const int b_roff = ((lane >> 4) & 1) * 8 + (lane & 7);
    const int b_coff = ((lane >> 3) & 1);

    uint32_t aF[2][4][4];   // fragment double buffer
    uint32_t bF[2][4][2];

    auto ldm_frags = [&](int d, int buf, int s) {
        const uint32_t sA = smem_tiles + buf * STAGE_BYTES;
        const uint32_t sB = sA + TILE_A_BYTES;
        #pragma unroll
        for (int mt = 0; mt < 4; mt++) {
            int r  = mbase + mt * 16 + a_roff;
            int ch = a_coff + 2 * s;
            uint32_t addr = sA + r * 128 + (((ch ^ (r & 7)) & 7) << 4);
            asm volatile("ldmatrix.sync.aligned.m8n8.x4.shared.b16 {%0,%1,%2,%3}, [%4];"
                         : "=r"(aF[d][mt][0]), "=r"(aF[d][mt][1]),
                           "=r"(aF[d][mt][2]), "=r"(aF[d][mt][3])
                         : "r"(addr));
        }
        #pragma unroll
        for (int p = 0; p < 2; p++) {
            int r  = nbase + p * 16 + b_roff;
            int ch = b_coff + 2 * s;
            uint32_t addr = sB + r * 128 + (((ch ^ (r & 7)) & 7) << 4);
            asm volatile("ldmatrix.sync.aligned.m8n8.x4.shared.b16 {%0,%1,%2,%3}, [%4];"
                         : "=r"(bF[d][2 * p][0]), "=r"(bF[d][2 * p][1]),
                           "=r"(bF[d][2 * p + 1][0]), "=r"(bF[d][2 * p + 1][1])
                         : "r"(addr));
        }
    };

    auto mma_all = [&](int d) {
        #pragma unroll
        for (int mt = 0; mt < 4; mt++)
            #pragma unroll
            for (int ntl = 0; ntl < 4; ntl++)
                asm volatile(
                    "mma.sync.aligned.m16n8k16.row.col.f16.f16.f16.f16 "
                    "{%0,%1}, {%2,%3,%4,%5}, {%6,%7}, {%0,%1};"
                    : "+r"(acc[mt][ntl][0]), "+r"(acc[mt][ntl][1])
                    : "r"(aF[d][mt][0]), "r"(aF[d][mt][1]),
                      "r"(aF[d][mt][2]), "r"(aF[d][mt][3]),
                      "r"(bF[d][ntl][0]), "r"(bF[d][ntl][1]));
    };

    asm volatile("cp.async.wait_group 2;" ::: "memory");   // stage 0 ready
    __syncthreads();
    ldm_frags(0, 0, 0);

    // 16 k16 steps; stage = kk>>2 (buffer stage%3), step-in-stage = kk&3
    #pragma unroll
    for (int kk = 0; kk < 16; kk++) {
        const int cur = kk & 1, nxt = cur ^ 1;
        const int stage = kk >> 2, spos = kk & 3;
        if (kk < 15) {
            if (spos == 3) {
                if (stage < 2) { asm volatile("cp.async.wait_group 1;" ::: "memory"); }
                else           { asm volatile("cp.async.wait_group 0;" ::: "memory"); }
                __syncthreads();
                if (stage == 0) load_stage(3, 0);
                ldm_frags(nxt, (stage + 1) % 3, 0);
            } else {
                ldm_frags(nxt, stage % 3, spos + 1);
            }
        }
        mma_all(cur);
    }

    // epilogue: unpack f16 acc -> dist -> hinge/mask -> sum over gi < gj
    const int gid = lane >> 2;
    const int tig = lane & 3;
    const bool need_mask = (bj < 2 * bi + 2);
    float lsum = 0.0f;
    #pragma unroll
    for (int mt = 0; mt < 4; mt++) {
        #pragma unroll
        for (int ntl = 0; ntl < 4; ntl++) {
            #pragma unroll
            for (int h = 0; h < 2; h++) {       // h=0: rows gid; h=1: rows gid+8
                float2 gp = __half22float2(*(const __half2*)&acc[mt][ntl][h]);
                int m = mbase + mt * 16 + gid + h * 8;
                float sqm = s_sqi[m];
                int   tm  = s_ti[m];
                #pragma unroll
                for (int q = 0; q < 2; q++) {
                    int nn = nbase + ntl * 8 + 2 * tig + q;
                    float g    = q ? gp.y : gp.x;
                    float dist = fmaf(-2.0f, g, sqm + s_sqj[nn]);
                    float val  = (tm == s_tj[nn]) ? dist : fmaxf(MARGIN - dist, 0.0f);
                    if (!need_mask || (iBase + m < jBase + nn)) lsum += val;
                }
            }
        }
    }

    s_red[tid] = lsum;
    __syncthreads();
    #pragma unroll
    for (int s = NTHREADS / 2; s > 32; s >>= 1) {
        if (tid < s) s_red[tid] += s_red[tid + s];
        __syncthreads();
    }
    if (tid < 32) {
        float v = s_red[tid] + s_red[tid + 32];
        #pragma unroll
        for (int o = 16; o > 0; o >>= 1) v += __shfl_xor_sync(0xffffffffu, v, o);
        if (tid == 0) atomicAdd(out, v * scale);
    }
}

extern "C" void kernel_launch(void* const* d_in, const int* in_sizes, int n_in,
                              void* d_out, int out_size) {
    const float* x   = (const float*)d_in[0];
    const void*  tgt = d_in[1];
    float*       out = (float*)d_out;

    int n = in_sizes[1];            // 8192
    int ntM = n / BM;               // 32
    int ntN = n / BN;               // 64
    int ngrid = ntM * ntN - ntM * (ntM - 1);   // 1056

    static int smem_set = 0;
    if (!smem_set) {
        cudaFuncSetAttribute(loss_kernel, cudaFuncAttributeMaxDynamicSharedMemorySize, SM_TOTAL);
        smem_set = 1;
    }

    cvtsq_kernel<<<(n + 7) / 8, 256>>>(x, (const unsigned int*)tgt, n, out);

    float scale = (float)(1.0 / ((double)n * ((double)n - 1.0)));
    loss_kernel<<<ngrid, NTHREADS, SM_TOTAL>>>(tgt, out, ntM, ntN, scale);
}

// round 11
// speedup vs baseline: 1.3882x; 1.1641x over previous
#include <cuda_runtime.h>
#include <cuda_fp16.h>
#include <cstdint>

#define N_MAX 8192
#define D_MAX 256
#define BM 128                    // CTA rows (i)
#define BN 128                    // CTA cols (j)
#define BK 64                     // f16 K per stage
#define NBUF 3                    // smem stage buffers
#define NTHREADS 256
#define MARGIN 0.5f

__device__ __half g_xh[N_MAX * D_MAX];
__device__ float g_sq[N_MAX];
__device__ int   g_is64;

// dynamic smem layout (bytes)
#define TILE_A_BYTES (BM * BK * 2)                  // 16384
#define TILE_B_BYTES (BN * BK * 2)                  // 16384
#define STAGE_BYTES  (TILE_A_BYTES + TILE_B_BYTES)  // 32768
#define SM_SQI   (NBUF * STAGE_BYTES)               // 98304
#define SM_SQJ   (SM_SQI + BM * 4)
#define SM_TI    (SM_SQJ + BN * 4)
#define SM_TJ    (SM_TI + BM * 4)
#define SM_RED   (SM_TJ + BN * 4)
#define SM_TOTAL (SM_RED + NTHREADS * 4)            // ~99.3 KB  -> 2 CTAs/SM

__device__ __forceinline__ uint32_t smem_u32(const void* p) {
    uint32_t a;
    asm("{ .reg .u64 t; cvta.to.shared.u64 t, %1; cvt.u32.u64 %0, t; }" : "=r"(a) : "l"(p));
    return a;
}

// ---------------------------------------------------------------------------
// fused prelim: zero out + int64 detect + exact fp32 norms + f16 copy
// ---------------------------------------------------------------------------
__global__ void cvtsq_kernel(const float* __restrict__ x,
                             const unsigned int* __restrict__ t, int n,
                             float* __restrict__ out) {
    if (blockIdx.x == 0 && threadIdx.x < 32) {
        int lane = threadIdx.x;
        unsigned bad = t[2 * lane + 1] | t[2 * (lane + 32) + 1];
        unsigned ball = __ballot_sync(0xffffffffu, bad != 0u);
        if (lane == 0) { g_is64 = (ball == 0u); out[0] = 0.0f; }
    }

    int row  = blockIdx.x * (blockDim.x >> 5) + (threadIdx.x >> 5);
    int lane = threadIdx.x & 31;
    if (row >= n) return;
    const float* p = x + (size_t)row * D_MAX;

    float4 v0 = *(const float4*)(p + lane * 4);
    float4 v1 = *(const float4*)(p + 128 + lane * 4);

    float s = v0.x * v0.x + v0.y * v0.y + v0.z * v0.z + v0.w * v0.w
            + v1.x * v1.x + v1.y * v1.y + v1.z * v1.z + v1.w * v1.w;
    #pragma unroll
    for (int o = 16; o > 0; o >>= 1) s += __shfl_xor_sync(0xffffffffu, s, o);
    if (lane == 0) g_sq[row] = s;

    __half* dst = g_xh + (size_t)row * D_MAX;
    *(__half2*)(dst + lane * 4)           = __floats2half2_rn(v0.x, v0.y);
    *(__half2*)(dst + lane * 4 + 2)       = __floats2half2_rn(v0.z, v0.w);
    *(__half2*)(dst + 128 + lane * 4)     = __floats2half2_rn(v1.x, v1.y);
    *(__half2*)(dst + 128 + lane * 4 + 2) = __floats2half2_rn(v1.z, v1.w);
}

// ---------------------------------------------------------------------------
// f16 mma.sync (f16 accum) fused gram + loss. CTA 128x128, 8 warps (2m x 4n),
// warp tile 64x32 (identical per-warp stream to R10). 2 CTAs resident per SM
// for stall decorrelation. 3-deep cp.async buffering + reg fragment dbl-buffer.
// smem rows: 128B stride; 16B chunk c of row r at r*128 + ((c^(r&7))<<4).
// ---------------------------------------------------------------------------
__global__ __launch_bounds__(NTHREADS, 2)
void loss_kernel(const void* __restrict__ tgt_raw, float* __restrict__ out,
                 int nt, float scale) {
    // triangular decode t -> (bi, bj), bj >= bi (validated R5-R7)
    const int t = blockIdx.x;
    int b = (int)((2.0f * nt + 1.0f -
                   sqrtf((2.0f * nt + 1.0f) * (2.0f * nt + 1.0f) - 8.0f * t)) * 0.5f);
    if (b < 0) b = 0;
    if (b > nt - 1) b = nt - 1;
    while (b + 1 <= nt - 1 && (b + 1) * nt - ((b + 1) * b) / 2 <= t) b++;
    while (b * nt - (b * (b - 1)) / 2 > t) b--;
    const int bi = b;
    const int bj = bi + (t - (bi * nt - (bi * (bi - 1)) / 2));

    extern __shared__ char smem[];
    float* s_sqi = (float*)(smem + SM_SQI);
    float* s_sqj = (float*)(smem + SM_SQJ);
    int*   s_ti  = (int*)(smem + SM_TI);
    int*   s_tj  = (int*)(smem + SM_TJ);
    float* s_red = (float*)(smem + SM_RED);

    const int tid  = threadIdx.x;
    const int wid  = tid >> 5;
    const int lane = tid & 31;
    const int iBase = bi * BM;
    const int jBase = bj * BN;

    const uint32_t smem_tiles = smem_u32(smem);
    const __half* xa = g_xh + (size_t)iBase * D_MAX;
    const __half* xb = g_xh + (size_t)jBase * D_MAX;

    // A: 1024 16B-chunks (4/thread), B: 1024 (4/thread); row=idx>>3, c=idx&7
    auto load_stage = [&](int kb, int buf) {
        const int k0 = kb * BK;
        const uint32_t sA = smem_tiles + buf * STAGE_BYTES;
        const uint32_t sB = sA + TILE_A_BYTES;
        #pragma unroll
        for (int u = 0; u < 4; u++) {
            int idx = tid * 4 + u;
            int row = idx >> 3;
            int c   = idx & 7;
            uint32_t sw = row * 128 + (((c ^ (row & 7)) & 7) << 4);
            asm volatile("cp.async.cg.shared.global [%0], [%1], 16;"
                         :: "r"(sA + sw), "l"((const void*)(xa + row * D_MAX + k0 + c * 8)) : "memory");
            asm volatile("cp.async.cg.shared.global [%0], [%1], 16;"
                         :: "r"(sB + sw), "l"((const void*)(xb + row * D_MAX + k0 + c * 8)) : "memory");
        }
        asm volatile("cp.async.commit_group;" ::: "memory");
    };

    load_stage(0, 0);
    load_stage(1, 1);
    load_stage(2, 2);

    {
        const long long* t64p = (const long long*)tgt_raw;
        const int*       t32p = (const int*)tgt_raw;
        const bool is64 = (g_is64 != 0);
        if (tid < BM) {
            s_sqi[tid] = g_sq[iBase + tid];
            s_ti[tid]  = is64 ? (int)t64p[iBase + tid] : t32p[iBase + tid];
        } else {
            int tt = tid - BM;
            s_sqj[tt] = g_sq[jBase + tt];
            s_tj[tt]  = is64 ? (int)t64p[jBase + tt] : t32p[jBase + tt];
        }
    }

    // warp grid 2m x 4n; warp tile 64 x 32
    const int mbase = (wid >> 2) * 64;
    const int nbase = (wid & 3) * 32;

    uint32_t acc[4][4][2];        // f16x2 pairs
    #pragma unroll
    for (int mt = 0; mt < 4; mt++)
        #pragma unroll
        for (int ntl = 0; ntl < 4; ntl++) { acc[mt][ntl][0] = 0u; acc[mt][ntl][1] = 0u; }

    const int a_roff = ((lane >> 3) & 1) * 8 + (lane & 7);
    const int a_coff = (lane >> 4);
    const int b_roff = ((lane >> 4) & 1) * 8 + (lane & 7);
    const int b_coff = ((lane >> 3) & 1);

    uint32_t aF[2][4][4];   // fragment double buffer
    uint32_t bF[2][4][2];

    auto ldm_frags = [&](int d, int buf, int s) {
        const uint32_t sA = smem_tiles + buf * STAGE_BYTES;
        const uint32_t sB = sA + TILE_A_BYTES;
        #pragma unroll
        for (int mt = 0; mt < 4; mt++) {
            int r  = mbase + mt * 16 + a_roff;
            int ch = a_coff + 2 * s;
            uint32_t addr = sA + r * 128 + (((ch ^ (r & 7)) & 7) << 4);
            asm volatile("ldmatrix.sync.aligned.m8n8.x4.shared.b16 {%0,%1,%2,%3}, [%4];"
                         : "=r"(aF[d][mt][0]), "=r"(aF[d][mt][1]),
                           "=r"(aF[d][mt][2]), "=r"(aF[d][mt][3])
                         : "r"(addr));
        }
        #pragma unroll
        for (int p = 0; p < 2; p++) {
            int r  = nbase + p * 16 + b_roff;
            int ch = b_coff + 2 * s;
            uint32_t addr = sB + r * 128 + (((ch ^ (r & 7)) & 7) << 4);
            asm volatile("ldmatrix.sync.aligned.m8n8.x4.shared.b16 {%0,%1,%2,%3}, [%4];"
                         : "=r"(bF[d][2 * p][0]), "=r"(bF[d][2 * p][1]),
                           "=r"(bF[d][2 * p + 1][0]), "=r"(bF[d][2 * p + 1][1])
                         : "r"(addr));
        }
    };

    auto mma_all = [&](int d) {
        #pragma unroll
        for (int mt = 0; mt < 4; mt++)
            #pragma unroll
            for (int ntl = 0; ntl < 4; ntl++)
                asm volatile(
                    "mma.sync.aligned.m16n8k16.row.col.f16.f16.f16.f16 "
                    "{%0,%1}, {%2,%3,%4,%5}, {%6,%7}, {%0,%1};"
                    : "+r"(acc[mt][ntl][0]), "+r"(acc[mt][ntl][1])
                    : "r"(aF[d][mt][0]), "r"(aF[d][mt][1]),
                      "r"(aF[d][mt][2]), "r"(aF[d][mt][3]),
                      "r"(bF[d][ntl][0]), "r"(bF[d][ntl][1]));
    };

    asm volatile("cp.async.wait_group 2;" ::: "memory");   // stage 0 ready
    __syncthreads();
    ldm_frags(0, 0, 0);

    // 16 k16 steps; stage = kk>>2 (buffer stage%3), step-in-stage = kk&3
    #pragma unroll
    for (int kk = 0; kk < 16; kk++) {
        const int cur = kk & 1, nxt = cur ^ 1;
        const int stage = kk >> 2, spos = kk & 3;
        if (kk < 15) {
            if (spos == 3) {
                if (stage < 2) { asm volatile("cp.async.wait_group 1;" ::: "memory"); }
                else           { asm volatile("cp.async.wait_group 0;" ::: "memory"); }
                __syncthreads();
                if (stage == 0) load_stage(3, 0);
                ldm_frags(nxt, (stage + 1) % 3, 0);
            } else {
                ldm_frags(nxt, stage % 3, spos + 1);
            }
        }
        mma_all(cur);
    }

    // epilogue: unpack f16 acc -> dist -> hinge/mask -> sum over gi < gj
    const int gid = lane >> 2;
    const int tig = lane & 3;
    const bool diag = (bi == bj);
    float lsum = 0.0f;
    #pragma unroll
    for (int mt = 0; mt < 4; mt++) {
        #pragma unroll
        for (int ntl = 0; ntl < 4; ntl++) {
            #pragma unroll
            for (int h = 0; h < 2; h++) {
                float2 gp = __half22float2(*(const __half2*)&acc[mt][ntl][h]);
                int m = mbase + mt * 16 + gid + h * 8;
                float sqm = s_sqi[m];
                int   tm  = s_ti[m];
                #pragma unroll
                for (int q = 0; q < 2; q++) {
                    int nn = nbase + ntl * 8 + 2 * tig + q;
                    float g    = q ? gp.y : gp.x;
                    float dist = fmaf(-2.0f, g, sqm + s_sqj[nn]);
                    float val  = (tm == s_tj[nn]) ? dist : fmaxf(MARGIN - dist, 0.0f);
                    if (!diag || (m < nn)) lsum += val;
                }
            }
        }
    }

    s_red[tid] = lsum;
    __syncthreads();
    #pragma unroll
    for (int s = NTHREADS / 2; s > 32; s >>= 1) {
        if (tid < s) s_red[tid] += s_red[tid + s];
        __syncthreads();
    }
    if (tid < 32) {
        float v = s_red[tid] + s_red[tid + 32];
        #pragma unroll
        for (int o = 16; o > 0; o >>= 1) v += __shfl_xor_sync(0xffffffffu, v, o);
        if (tid == 0) atomicAdd(out, v * scale);
    }
}

extern "C" void kernel_launch(void* const* d_in, const int* in_sizes, int n_in,
                              void* d_out, int out_size) {
    const float* x   = (const float*)d_in[0];
    const void*  tgt = d_in[1];
    float*       out = (float*)d_out;

    int n = in_sizes[1];            // 8192
    int nt = n / BM;                // 64
    int ntri = nt * (nt + 1) / 2;   // 2080

    static int smem_set = 0;
    if (!smem_set) {
        cudaFuncSetAttribute(loss_kernel, cudaFuncAttributeMaxDynamicSharedMemorySize, SM_TOTAL);
        smem_set = 1;
    }

    cvtsq_kernel<<<(n + 7) / 8, 256>>>(x, (const unsigned int*)tgt, n, out);

    float scale = (float)(1.0 / ((double)n * ((double)n - 1.0)));
    loss_kernel<<<ntri, NTHREADS, SM_TOTAL>>>(tgt, out, nt, scale);
}